// round 7
// baseline (speedup 1.0000x reference)
#include <cuda_runtime.h>
#include <cuda_bf16.h>
#include <math.h>
#include <stdint.h>

// Problem constants
#define Bq 2
#define Sq 2048
#define Dm 1024
#define Hn 16
#define DP 64
#define BH (Bq * Hn)       // 32
#define Mrows (Bq * Sq)    // 4096

// Scratch (device globals: no allocation allowed)
__device__ float g_qh[BH * Sq * DP];    // [b*H+h][s][d]
__device__ float g_kh[BH * Sq * DP];
__device__ float g_vh[BH * Sq * DP];
__device__ float g_attn[Mrows * Dm];    // attention output, [b][s][h*64+d]
__device__ float g_rowsum[BH * Sq];     // softmax denominators

__device__ __forceinline__ uint32_t smem_u32(const void* p) {
    uint32_t a;
    asm("{ .reg .u64 t; cvta.to.shared.u64 t, %1; cvt.u32.u64 %0, t; }"
        : "=r"(a) : "l"(p));
    return a;
}
__device__ __forceinline__ void ldmat4(uint32_t* f, uint32_t addr) {
    asm volatile("ldmatrix.sync.aligned.m8n8.x4.shared.b16 {%0,%1,%2,%3}, [%4];"
                 : "=r"(f[0]), "=r"(f[1]), "=r"(f[2]), "=r"(f[3]) : "r"(addr));
}
__device__ __forceinline__ void mma16816(float* d, const uint32_t* a,
                                         uint32_t b0, uint32_t b1) {
    asm volatile(
        "mma.sync.aligned.m16n8k16.row.col.f32.bf16.bf16.f32 "
        "{%0,%1,%2,%3}, {%4,%5,%6,%7}, {%8,%9}, {%0,%1,%2,%3};"
        : "+f"(d[0]), "+f"(d[1]), "+f"(d[2]), "+f"(d[3])
        : "r"(a[0]), "r"(a[1]), "r"(a[2]), "r"(a[3]), "r"(b0), "r"(b1));
}
__device__ __forceinline__ uint32_t pack2bf16(float x, float y) {
    __nv_bfloat162 h = __floats2bfloat162_rn(x, y);
    return *(uint32_t*)&h;
}
__device__ __forceinline__ float bf16hi(float x) {
    return __bfloat162float(__float2bfloat16_rn(x));
}

// ===========================================================================
// mma.sync bf16-split GEMM: C = A[4096,1024] @ W[1024,1024]^T + bias.
// fp32 = hi + lo (bf16 planes); products hh + hl + lh (ll dropped, ~2^-16).
// CTA 128x128, BK=32, 8 warps of 32m x 64n. Smem rows padded to 40 bf16
// (80 B) -> the 8 rows of each ldmatrix quarter hit distinct 16B groups.
// ===========================================================================
#define LDB 40   // bf16 elements per smem row (32 data + 8 pad)

__global__ __launch_bounds__(256, 2) void tc_gemm(
    const float* __restrict__ A, const float* __restrict__ W,
    const float* __restrict__ bias, float* __restrict__ C, int headSplit)
{
    __shared__ __nv_bfloat16 AH[128 * LDB];
    __shared__ __nv_bfloat16 AL[128 * LDB];
    __shared__ __nv_bfloat16 WH[128 * LDB];
    __shared__ __nv_bfloat16 WL[128 * LDB];

    const int tid = threadIdx.x;
    const int wid = tid >> 5, lane = tid & 31;
    const int wm = wid & 3, wn = wid >> 2;       // warp tile: rows wm*32, cols wn*64
    const int m0 = blockIdx.y * 128, n0 = blockIdx.x * 128;

    const uint32_t sAH = smem_u32(AH), sAL = smem_u32(AL);
    const uint32_t sWH = smem_u32(WH), sWL = smem_u32(WL);

    // loader assignment: row r = tid>>1, k-half ko = (tid&1)*16
    const int lr = tid >> 1;
    const int lko = (tid & 1) * 16;
    const float* aptr = A + (size_t)(m0 + lr) * Dm + lko;
    const float* wptr = W + (size_t)(n0 + lr) * Dm + lko;
    __nv_bfloat16* pAH = AH + lr * LDB + lko;
    __nv_bfloat16* pAL = AL + lr * LDB + lko;
    __nv_bfloat16* pWH = WH + lr * LDB + lko;
    __nv_bfloat16* pWL = WL + lr * LDB + lko;

    float acc[2][8][4];
#pragma unroll
    for (int i = 0; i < 2; i++)
#pragma unroll
        for (int j = 0; j < 8; j++)
#pragma unroll
            for (int x = 0; x < 4; x++) acc[i][j][x] = 0.0f;

    // ldmatrix lane addressing offsets
    const int lrow = lane & 15;             // row within 16-row tile
    const int lcol = (lane >> 4) << 3;      // 0 or 8 (k offset)

    for (int t = 0; t < 32; t++) {
        const int kt = t * 32;
        // ---- load + split-convert 128x32 of A and W ----
        {
            float v[16];
#pragma unroll
            for (int q4 = 0; q4 < 4; q4++)
                *(float4*)&v[q4 * 4] = *(const float4*)&aptr[kt + q4 * 4];
            uint32_t hi[8], lo[8];
#pragma unroll
            for (int e = 0; e < 8; e++) {
                float h0 = bf16hi(v[2 * e]), h1 = bf16hi(v[2 * e + 1]);
                hi[e] = pack2bf16(v[2 * e], v[2 * e + 1]);
                lo[e] = pack2bf16(v[2 * e] - h0, v[2 * e + 1] - h1);
            }
            *(uint4*)pAH = make_uint4(hi[0], hi[1], hi[2], hi[3]);
            *(uint4*)(pAH + 8) = make_uint4(hi[4], hi[5], hi[6], hi[7]);
            *(uint4*)pAL = make_uint4(lo[0], lo[1], lo[2], lo[3]);
            *(uint4*)(pAL + 8) = make_uint4(lo[4], lo[5], lo[6], lo[7]);

#pragma unroll
            for (int q4 = 0; q4 < 4; q4++)
                *(float4*)&v[q4 * 4] = *(const float4*)&wptr[kt + q4 * 4];
#pragma unroll
            for (int e = 0; e < 8; e++) {
                float h0 = bf16hi(v[2 * e]), h1 = bf16hi(v[2 * e + 1]);
                hi[e] = pack2bf16(v[2 * e], v[2 * e + 1]);
                lo[e] = pack2bf16(v[2 * e] - h0, v[2 * e + 1] - h1);
            }
            *(uint4*)pWH = make_uint4(hi[0], hi[1], hi[2], hi[3]);
            *(uint4*)(pWH + 8) = make_uint4(hi[4], hi[5], hi[6], hi[7]);
            *(uint4*)pWL = make_uint4(lo[0], lo[1], lo[2], lo[3]);
            *(uint4*)(pWL + 8) = make_uint4(lo[4], lo[5], lo[6], lo[7]);
        }
        __syncthreads();

        // ---- compute: two k16 steps ----
#pragma unroll
        for (int kk = 0; kk < 32; kk += 16) {
            uint32_t ah[2][4], al[2][4];
#pragma unroll
            for (int mt = 0; mt < 2; mt++) {
                uint32_t off = (uint32_t)((wm * 32 + mt * 16 + lrow) * LDB + kk + lcol) * 2;
                ldmat4(ah[mt], sAH + off);
                ldmat4(al[mt], sAL + off);
            }
#pragma unroll
            for (int nt4 = 0; nt4 < 4; nt4++) {
                uint32_t off = (uint32_t)((wn * 64 + nt4 * 16 + lrow) * LDB + kk + lcol) * 2;
                uint32_t wh[4], wl[4];
                ldmat4(wh, sWH + off);
                ldmat4(wl, sWL + off);
#pragma unroll
                for (int mt = 0; mt < 2; mt++) {
                    mma16816(acc[mt][2 * nt4],     ah[mt], wh[0], wh[2]);
                    mma16816(acc[mt][2 * nt4 + 1], ah[mt], wh[1], wh[3]);
                    mma16816(acc[mt][2 * nt4],     ah[mt], wl[0], wl[2]);
                    mma16816(acc[mt][2 * nt4 + 1], ah[mt], wl[1], wl[3]);
                    mma16816(acc[mt][2 * nt4],     al[mt], wh[0], wh[2]);
                    mma16816(acc[mt][2 * nt4 + 1], al[mt], wh[1], wh[3]);
                }
            }
        }
        __syncthreads();
    }

    // ---- epilogue: +bias, store ----
    const int lrq = lane >> 2;          // 0..7
    const int lc2 = (lane & 3) * 2;     // 0,2,4,6
#pragma unroll
    for (int mt = 0; mt < 2; mt++) {
#pragma unroll
        for (int nt = 0; nt < 8; nt++) {
            int col = n0 + wn * 64 + nt * 8 + lc2;
            float b0 = bias[col], b1 = bias[col + 1];
#pragma unroll
            for (int half = 0; half < 2; half++) {
                int row = m0 + wm * 32 + mt * 16 + lrq + half * 8;
                float2 o;
                o.x = acc[mt][nt][half * 2 + 0] + b0;
                o.y = acc[mt][nt][half * 2 + 1] + b1;
                if (!headSplit) {
                    *(float2*)&C[(size_t)row * Dm + col] = o;
                } else {
                    int bb = row >> 11, s = row & 2047;
                    int h = col >> 6, dd = col & 63;
                    *(float2*)&C[((size_t)(bb * Hn + h) * Sq + s) * DP + dd] = o;
                }
            }
        }
    }
}

// ---------------------------------------------------------------------------
// Fused attention (SIMT, unchanged from R2): 128q x 128k tiles.
// ---------------------------------------------------------------------------
#define LDQ 132
#define LDV 68
__global__ __launch_bounds__(256, 1) void attn_kernel(
    const float* __restrict__ mask, float* __restrict__ wout)
{
    extern __shared__ float smf[];
    float* Qs = smf;
    float* Ks = Qs + 64 * LDQ;
    float* Vs = Ks + 64 * LDQ;
    float* Es = Vs + 128 * LDV;

    int tid = threadIdx.x;
    int ty = tid >> 4, tx = tid & 15;
    int qb = blockIdx.x;
    int bh = blockIdx.y;
    int b  = bh >> 4;
    int h  = bh & 15;

    const float* qbase = g_qh + ((size_t)bh * Sq + qb * 128) * DP;
    const float* kbase = g_kh + (size_t)bh * Sq * DP;
    const float* vbase = g_vh + (size_t)bh * Sq * DP;
    const float* mbase = mask + ((size_t)b * Sq + qb * 128) * Sq;
    float*       wbase = wout + ((size_t)bh * Sq + qb * 128) * Sq;

#pragma unroll
    for (int l = 0; l < 8; l++) {
        int t = tid + l * 256;
        int r = t >> 4, d4 = (t & 15) * 4;
        float4 v = *(const float4*)&qbase[r * DP + d4];
        Qs[(d4 + 0) * LDQ + r] = v.x; Qs[(d4 + 1) * LDQ + r] = v.y;
        Qs[(d4 + 2) * LDQ + r] = v.z; Qs[(d4 + 3) * LDQ + r] = v.w;
    }

    int r0 = ty * 8;
    int c0 = tx * 4;

    float acc[8][4];
#pragma unroll
    for (int i = 0; i < 8; i++)
#pragma unroll
        for (int j = 0; j < 4; j++) acc[i][j] = 0.0f;
    float rsum[8];
#pragma unroll
    for (int i = 0; i < 8; i++) rsum[i] = 0.0f;

    for (int kt = 0; kt < Sq; kt += 128) {
        const float* kb = kbase + (size_t)kt * DP;
        const float* vb = vbase + (size_t)kt * DP;
#pragma unroll
        for (int l = 0; l < 8; l++) {
            int t = tid + l * 256;
            int r = t >> 4, d4 = (t & 15) * 4;
            float4 kv = *(const float4*)&kb[r * DP + d4];
            Ks[(d4 + 0) * LDQ + r] = kv.x; Ks[(d4 + 1) * LDQ + r] = kv.y;
            Ks[(d4 + 2) * LDQ + r] = kv.z; Ks[(d4 + 3) * LDQ + r] = kv.w;
            float4 vv = *(const float4*)&vb[r * DP + d4];
            *(float4*)&Vs[r * LDV + d4] = vv;
        }
        __syncthreads();

        float s[8][8];
#pragma unroll
        for (int i = 0; i < 8; i++)
#pragma unroll
            for (int j = 0; j < 8; j++) s[i][j] = 0.0f;
#pragma unroll 4
        for (int d = 0; d < 64; d++) {
            float a[8], kkv[8];
            *(float4*)&a[0]   = *(float4*)&Qs[d * LDQ + r0];
            *(float4*)&a[4]   = *(float4*)&Qs[d * LDQ + r0 + 4];
            *(float4*)&kkv[0] = *(float4*)&Ks[d * LDQ + c0];
            *(float4*)&kkv[4] = *(float4*)&Ks[d * LDQ + 64 + c0];
#pragma unroll
            for (int i = 0; i < 8; i++)
#pragma unroll
                for (int j = 0; j < 8; j++) s[i][j] += a[i] * kkv[j];
        }

#pragma unroll
        for (int i = 0; i < 8; i++) {
            size_t ro = (size_t)(r0 + i) * Sq + kt;
            float4 m0v = *(const float4*)&mbase[ro + c0];
            float4 m1v = *(const float4*)&mbase[ro + 64 + c0];
            float4 e0, e1;
            e0.x = __expf(s[i][0] * 0.125f + m0v.x * (-1e9f));
            e0.y = __expf(s[i][1] * 0.125f + m0v.y * (-1e9f));
            e0.z = __expf(s[i][2] * 0.125f + m0v.z * (-1e9f));
            e0.w = __expf(s[i][3] * 0.125f + m0v.w * (-1e9f));
            e1.x = __expf(s[i][4] * 0.125f + m1v.x * (-1e9f));
            e1.y = __expf(s[i][5] * 0.125f + m1v.y * (-1e9f));
            e1.z = __expf(s[i][6] * 0.125f + m1v.z * (-1e9f));
            e1.w = __expf(s[i][7] * 0.125f + m1v.w * (-1e9f));
            *(float4*)&wbase[ro + c0]      = e0;
            *(float4*)&wbase[ro + 64 + c0] = e1;
            *(float4*)&Es[(r0 + i) * LDQ + c0]      = e0;
            *(float4*)&Es[(r0 + i) * LDQ + 64 + c0] = e1;
            rsum[i] += (e0.x + e0.y + e0.z + e0.w) + (e1.x + e1.y + e1.z + e1.w);
        }
        __syncthreads();

#pragma unroll 4
        for (int kk = 0; kk < 128; kk += 4) {
            float4 v0 = *(float4*)&Vs[(kk + 0) * LDV + c0];
            float4 v1 = *(float4*)&Vs[(kk + 1) * LDV + c0];
            float4 v2 = *(float4*)&Vs[(kk + 2) * LDV + c0];
            float4 v3 = *(float4*)&Vs[(kk + 3) * LDV + c0];
#pragma unroll
            for (int i = 0; i < 8; i++) {
                float4 e4 = *(float4*)&Es[(r0 + i) * LDQ + kk];
                acc[i][0] += e4.x * v0.x + e4.y * v1.x + e4.z * v2.x + e4.w * v3.x;
                acc[i][1] += e4.x * v0.y + e4.y * v1.y + e4.z * v2.y + e4.w * v3.y;
                acc[i][2] += e4.x * v0.z + e4.y * v1.z + e4.z * v2.z + e4.w * v3.z;
                acc[i][3] += e4.x * v0.w + e4.y * v1.w + e4.z * v2.w + e4.w * v3.w;
            }
        }
        __syncthreads();
    }

#pragma unroll
    for (int i = 0; i < 8; i++) Es[(r0 + i) * LDQ + tx] = rsum[i];
    __syncthreads();

#pragma unroll
    for (int i = 0; i < 8; i++) {
        float ssum = 0.0f;
#pragma unroll
        for (int t = 0; t < 16; t++) ssum += Es[(r0 + i) * LDQ + t];
        float inv = 1.0f / ssum;
        if (tx == 0) g_rowsum[(size_t)bh * Sq + qb * 128 + r0 + i] = ssum;
        size_t obase = ((size_t)b * Sq + qb * 128 + r0 + i) * Dm + h * DP + c0;
        float4 o;
        o.x = acc[i][0] * inv; o.y = acc[i][1] * inv;
        o.z = acc[i][2] * inv; o.w = acc[i][3] * inv;
        *(float4*)&g_attn[obase] = o;
    }
}

// ---------------------------------------------------------------------------
__global__ __launch_bounds__(128) void norm_kernel(float* __restrict__ w)
{
    int row = blockIdx.x;
    float inv = 1.0f / g_rowsum[row];
    float4* p = (float4*)(w + (size_t)row * Sq);
#pragma unroll
    for (int t = threadIdx.x; t < Sq / 4; t += 128) {
        float4 v = p[t];
        v.x *= inv; v.y *= inv; v.z *= inv; v.w *= inv;
        p[t] = v;
    }
}

// ---------------------------------------------------------------------------
extern "C" void kernel_launch(void* const* d_in, const int* in_sizes, int n_in,
                              void* d_out, int out_size)
{
    const float* q    = (const float*)d_in[0];
    const float* v    = (const float*)d_in[1];
    const float* k    = (const float*)d_in[2];
    const float* mask = (const float*)d_in[3];
    const float* wq_w = (const float*)d_in[4];
    const float* wq_b = (const float*)d_in[5];
    const float* wk_w = (const float*)d_in[6];
    const float* wk_b = (const float*)d_in[7];
    const float* wv_w = (const float*)d_in[8];
    const float* wv_b = (const float*)d_in[9];
    const float* dw   = (const float*)d_in[10];
    const float* db   = (const float*)d_in[11];

    float* out     = (float*)d_out;
    float* weights = out + (size_t)Mrows * Dm;

    float *qh, *kh, *vh, *attn;
    cudaGetSymbolAddress((void**)&qh,   g_qh);
    cudaGetSymbolAddress((void**)&kh,   g_kh);
    cudaGetSymbolAddress((void**)&vh,   g_vh);
    cudaGetSymbolAddress((void**)&attn, g_attn);

    dim3 g(Dm / 128, Mrows / 128);   // (8, 32)

    tc_gemm<<<g, 256>>>(q, wq_w, wq_b, qh, 1);
    tc_gemm<<<g, 256>>>(k, wk_w, wk_b, kh, 1);
    tc_gemm<<<g, 256>>>(v, wv_w, wv_b, vh, 1);

    int smem = (64 * LDQ + 64 * LDQ + 128 * LDV + 128 * LDQ) * sizeof(float);
    cudaFuncSetAttribute(attn_kernel, cudaFuncAttributeMaxDynamicSharedMemorySize, smem);
    attn_kernel<<<dim3(Sq / 128, BH), 256, smem>>>(mask, weights);

    norm_kernel<<<BH * Sq, 128>>>(weights);

    tc_gemm<<<g, 256>>>(attn, dw, db, out, 0);
}

// round 8
// speedup vs baseline: 1.3993x; 1.3993x over previous
#include <cuda_runtime.h>
#include <cuda_bf16.h>
#include <math.h>
#include <stdint.h>

// Problem constants
#define Bq 2
#define Sq 2048
#define Dm 1024
#define Hn 16
#define DP 64
#define BH (Bq * Hn)       // 32
#define Mrows (Bq * Sq)    // 4096

// Scratch (device globals: no allocation allowed)
__device__ __nv_bfloat16 g_qhh[BH * Sq * DP];   // [bh][s][d] hi plane
__device__ __nv_bfloat16 g_qhl[BH * Sq * DP];   // lo plane
__device__ __nv_bfloat16 g_khh[BH * Sq * DP];
__device__ __nv_bfloat16 g_khl[BH * Sq * DP];
__device__ __nv_bfloat16 g_vhh[BH * Sq * DP];
__device__ __nv_bfloat16 g_vhl[BH * Sq * DP];
__device__ float g_attn[Mrows * Dm];    // attention output, [b][s][h*64+d]
__device__ float g_rowsum[BH * Sq];     // softmax denominators

__device__ __forceinline__ uint32_t smem_u32(const void* p) {
    uint32_t a;
    asm("{ .reg .u64 t; cvta.to.shared.u64 t, %1; cvt.u32.u64 %0, t; }"
        : "=r"(a) : "l"(p));
    return a;
}
__device__ __forceinline__ void ldmat4(uint32_t* f, uint32_t addr) {
    asm volatile("ldmatrix.sync.aligned.m8n8.x4.shared.b16 {%0,%1,%2,%3}, [%4];"
                 : "=r"(f[0]), "=r"(f[1]), "=r"(f[2]), "=r"(f[3]) : "r"(addr));
}
__device__ __forceinline__ void ldmat4t(uint32_t* f, uint32_t addr) {
    asm volatile("ldmatrix.sync.aligned.m8n8.x4.trans.shared.b16 {%0,%1,%2,%3}, [%4];"
                 : "=r"(f[0]), "=r"(f[1]), "=r"(f[2]), "=r"(f[3]) : "r"(addr));
}
__device__ __forceinline__ void mma16816(float* d, const uint32_t* a,
                                         uint32_t b0, uint32_t b1) {
    asm volatile(
        "mma.sync.aligned.m16n8k16.row.col.f32.bf16.bf16.f32 "
        "{%0,%1,%2,%3}, {%4,%5,%6,%7}, {%8,%9}, {%0,%1,%2,%3};"
        : "+f"(d[0]), "+f"(d[1]), "+f"(d[2]), "+f"(d[3])
        : "r"(a[0]), "r"(a[1]), "r"(a[2]), "r"(a[3]), "r"(b0), "r"(b1));
}
__device__ __forceinline__ uint32_t pack2bf16(float x, float y) {
    __nv_bfloat162 h = __floats2bfloat162_rn(x, y);
    return *(uint32_t*)&h;
}
__device__ __forceinline__ float bf16hi(float x) {
    return __bfloat162float(__float2bfloat16_rn(x));
}

// ===========================================================================
// mma.sync bf16-split GEMM: C = A[4096,1024] @ W[1024,1024]^T + bias.
// headSplit=1: write head-split bf16 hi/lo planes (CH/CL); else fp32 C.
// ===========================================================================
#define LDB 40   // bf16 elements per smem row (32 data + 8 pad)

__global__ __launch_bounds__(256, 2) void tc_gemm(
    const float* __restrict__ A, const float* __restrict__ W,
    const float* __restrict__ bias, float* __restrict__ C,
    __nv_bfloat16* __restrict__ CH, __nv_bfloat16* __restrict__ CL,
    int headSplit)
{
    __shared__ __nv_bfloat16 AH[128 * LDB];
    __shared__ __nv_bfloat16 AL[128 * LDB];
    __shared__ __nv_bfloat16 WH[128 * LDB];
    __shared__ __nv_bfloat16 WL[128 * LDB];

    const int tid = threadIdx.x;
    const int wid = tid >> 5, lane = tid & 31;
    const int wm = wid & 3, wn = wid >> 2;
    const int m0 = blockIdx.y * 128, n0 = blockIdx.x * 128;

    const uint32_t sAH = smem_u32(AH), sAL = smem_u32(AL);
    const uint32_t sWH = smem_u32(WH), sWL = smem_u32(WL);

    const int lr = tid >> 1;
    const int lko = (tid & 1) * 16;
    const float* aptr = A + (size_t)(m0 + lr) * Dm + lko;
    const float* wptr = W + (size_t)(n0 + lr) * Dm + lko;
    __nv_bfloat16* pAH = AH + lr * LDB + lko;
    __nv_bfloat16* pAL = AL + lr * LDB + lko;
    __nv_bfloat16* pWH = WH + lr * LDB + lko;
    __nv_bfloat16* pWL = WL + lr * LDB + lko;

    float acc[2][8][4];
#pragma unroll
    for (int i = 0; i < 2; i++)
#pragma unroll
        for (int j = 0; j < 8; j++)
#pragma unroll
            for (int x = 0; x < 4; x++) acc[i][j][x] = 0.0f;

    const int lrow = lane & 15;
    const int lcol = (lane >> 4) << 3;

    for (int t = 0; t < 32; t++) {
        const int kt = t * 32;
        {
            float v[16];
#pragma unroll
            for (int q4 = 0; q4 < 4; q4++)
                *(float4*)&v[q4 * 4] = *(const float4*)&aptr[kt + q4 * 4];
            uint32_t hi[8], lo[8];
#pragma unroll
            for (int e = 0; e < 8; e++) {
                float h0 = bf16hi(v[2 * e]), h1 = bf16hi(v[2 * e + 1]);
                hi[e] = pack2bf16(v[2 * e], v[2 * e + 1]);
                lo[e] = pack2bf16(v[2 * e] - h0, v[2 * e + 1] - h1);
            }
            *(uint4*)pAH = make_uint4(hi[0], hi[1], hi[2], hi[3]);
            *(uint4*)(pAH + 8) = make_uint4(hi[4], hi[5], hi[6], hi[7]);
            *(uint4*)pAL = make_uint4(lo[0], lo[1], lo[2], lo[3]);
            *(uint4*)(pAL + 8) = make_uint4(lo[4], lo[5], lo[6], lo[7]);

#pragma unroll
            for (int q4 = 0; q4 < 4; q4++)
                *(float4*)&v[q4 * 4] = *(const float4*)&wptr[kt + q4 * 4];
#pragma unroll
            for (int e = 0; e < 8; e++) {
                float h0 = bf16hi(v[2 * e]), h1 = bf16hi(v[2 * e + 1]);
                hi[e] = pack2bf16(v[2 * e], v[2 * e + 1]);
                lo[e] = pack2bf16(v[2 * e] - h0, v[2 * e + 1] - h1);
            }
            *(uint4*)pWH = make_uint4(hi[0], hi[1], hi[2], hi[3]);
            *(uint4*)(pWH + 8) = make_uint4(hi[4], hi[5], hi[6], hi[7]);
            *(uint4*)pWL = make_uint4(lo[0], lo[1], lo[2], lo[3]);
            *(uint4*)(pWL + 8) = make_uint4(lo[4], lo[5], lo[6], lo[7]);
        }
        __syncthreads();

#pragma unroll
        for (int kk = 0; kk < 32; kk += 16) {
            uint32_t ah[2][4], al[2][4];
#pragma unroll
            for (int mt = 0; mt < 2; mt++) {
                uint32_t off = (uint32_t)((wm * 32 + mt * 16 + lrow) * LDB + kk + lcol) * 2;
                ldmat4(ah[mt], sAH + off);
                ldmat4(al[mt], sAL + off);
            }
#pragma unroll
            for (int nt4 = 0; nt4 < 4; nt4++) {
                uint32_t off = (uint32_t)((wn * 64 + nt4 * 16 + lrow) * LDB + kk + lcol) * 2;
                uint32_t wh[4], wl[4];
                ldmat4(wh, sWH + off);
                ldmat4(wl, sWL + off);
#pragma unroll
                for (int mt = 0; mt < 2; mt++) {
                    mma16816(acc[mt][2 * nt4],     ah[mt], wh[0], wh[2]);
                    mma16816(acc[mt][2 * nt4 + 1], ah[mt], wh[1], wh[3]);
                    mma16816(acc[mt][2 * nt4],     ah[mt], wl[0], wl[2]);
                    mma16816(acc[mt][2 * nt4 + 1], ah[mt], wl[1], wl[3]);
                    mma16816(acc[mt][2 * nt4],     al[mt], wh[0], wh[2]);
                    mma16816(acc[mt][2 * nt4 + 1], al[mt], wh[1], wh[3]);
                }
            }
        }
        __syncthreads();
    }

    const int lrq = lane >> 2;
    const int lc2 = (lane & 3) * 2;
#pragma unroll
    for (int mt = 0; mt < 2; mt++) {
#pragma unroll
        for (int nt = 0; nt < 8; nt++) {
            int col = n0 + wn * 64 + nt * 8 + lc2;
            float b0 = bias[col], b1 = bias[col + 1];
#pragma unroll
            for (int half = 0; half < 2; half++) {
                int row = m0 + wm * 32 + mt * 16 + lrq + half * 8;
                float ox = acc[mt][nt][half * 2 + 0] + b0;
                float oy = acc[mt][nt][half * 2 + 1] + b1;
                if (!headSplit) {
                    *(float2*)&C[(size_t)row * Dm + col] = make_float2(ox, oy);
                } else {
                    int bb = row >> 11, sI = row & 2047;
                    int h = col >> 6, dd = col & 63;
                    size_t base = ((size_t)(bb * Hn + h) * Sq + sI) * DP + dd;
                    float h0 = bf16hi(ox), h1 = bf16hi(oy);
                    *(uint32_t*)&CH[base] = pack2bf16(ox, oy);
                    *(uint32_t*)&CL[base] = pack2bf16(ox - h0, oy - h1);
                }
            }
        }
    }
}

// ===========================================================================
// Tensor-core fused attention. CTA = (bh, 128 q-rows); 16 k-tiles of 128.
// QK^T: 3 bf16 planes; AV: 3 bf16 planes (E split in-kernel).
// 8 warps as 4m x 2n. Unnormalized e -> wout; rowsum -> g_rowsum.
// ===========================================================================
#define KLD 72    // bf16 stride for Q/K/V smem rows (64 + 8 pad)
#define ELD 136   // bf16 stride for E rows (128 + 8 pad)
// smem byte offsets
#define OQH 0
#define OQL (OQH + 128 * KLD * 2)
#define OKH (OQL + 128 * KLD * 2)
#define OKL (OKH + 128 * KLD * 2)
#define OVH (OKL + 128 * KLD * 2)
#define OVL (OVH + 128 * KLD * 2)
#define OEH (OVL + 128 * KLD * 2)
#define OEL (OEH + 128 * ELD * 2)
#define ORS (OEL + 128 * ELD * 2)
#define ASMEM (ORS + 128 * 2 * 4)     // 181248 B

__global__ __launch_bounds__(256, 1) void attn_tc(
    const float* __restrict__ mask, float* __restrict__ wout)
{
    extern __shared__ char smb[];
    const uint32_t sb = smem_u32(smb);
    float* RS = (float*)(smb + ORS);

    const int tid = threadIdx.x;
    const int wid = tid >> 5, lane = tid & 31;
    const int wm = wid & 3, wn = wid >> 2;
    const int qb = blockIdx.x;          // 0..15
    const int bh = blockIdx.y;          // 0..31
    const int b = bh >> 4, h = bh & 15;

    const int lrow = lane & 15;
    const int lcol = (lane >> 4) << 3;
    const int lrq = lane >> 2;
    const int lc2 = (lane & 3) * 2;

    // ---- load Q hi/lo (128 x 64 bf16 each) ----
    {
        const uint4* qH = (const uint4*)(g_qhh + ((size_t)bh * Sq + qb * 128) * DP);
        const uint4* qL = (const uint4*)(g_qhl + ((size_t)bh * Sq + qb * 128) * DP);
#pragma unroll
        for (int i = 0; i < 4; i++) {
            int id = tid + i * 256;          // 0..1023
            int r = id >> 3, c = id & 7;
            *(uint4*)(smb + OQH + (r * KLD + c * 8) * 2) = qH[r * 8 + c];
            *(uint4*)(smb + OQL + (r * KLD + c * 8) * 2) = qL[r * 8 + c];
        }
    }

    float accA[2][4][4];
#pragma unroll
    for (int i = 0; i < 2; i++)
#pragma unroll
        for (int j = 0; j < 4; j++)
#pragma unroll
            for (int x = 0; x < 4; x++) accA[i][j][x] = 0.0f;
    float rsum[2][2] = {{0.f, 0.f}, {0.f, 0.f}};

    const uint4* kH = (const uint4*)(g_khh + (size_t)bh * Sq * DP);
    const uint4* kL = (const uint4*)(g_khl + (size_t)bh * Sq * DP);
    const uint4* vH = (const uint4*)(g_vhh + (size_t)bh * Sq * DP);
    const uint4* vL = (const uint4*)(g_vhl + (size_t)bh * Sq * DP);

    for (int kt = 0; kt < 16; kt++) {
        const int ktbase = kt * 128;
        // ---- load K/V hi/lo tiles (128 x 64 each) ----
#pragma unroll
        for (int i = 0; i < 4; i++) {
            int id = tid + i * 256;
            int r = id >> 3, c = id & 7;
            size_t gi = (size_t)(ktbase + r) * 8 + c;
            *(uint4*)(smb + OKH + (r * KLD + c * 8) * 2) = kH[gi];
            *(uint4*)(smb + OKL + (r * KLD + c * 8) * 2) = kL[gi];
            *(uint4*)(smb + OVH + (r * KLD + c * 8) * 2) = vH[gi];
            *(uint4*)(smb + OVL + (r * KLD + c * 8) * 2) = vL[gi];
        }
        __syncthreads();

        // ---- QK^T: s[2 mt][8 nt][4] ----
        float s[2][8][4];
#pragma unroll
        for (int i = 0; i < 2; i++)
#pragma unroll
            for (int j = 0; j < 8; j++)
#pragma unroll
                for (int x = 0; x < 4; x++) s[i][j][x] = 0.0f;

#pragma unroll
        for (int kk = 0; kk < 64; kk += 16) {
            uint32_t ah[2][4], al[2][4];
#pragma unroll
            for (int mt = 0; mt < 2; mt++) {
                uint32_t off = (uint32_t)((wm * 32 + mt * 16 + lrow) * KLD + kk + lcol) * 2;
                ldmat4(ah[mt], sb + OQH + off);
                ldmat4(al[mt], sb + OQL + off);
            }
#pragma unroll
            for (int nt4 = 0; nt4 < 4; nt4++) {
                uint32_t off = (uint32_t)((wn * 64 + nt4 * 16 + lrow) * KLD + kk + lcol) * 2;
                uint32_t bh4[4], bl4[4];
                ldmat4(bh4, sb + OKH + off);
                ldmat4(bl4, sb + OKL + off);
#pragma unroll
                for (int mt = 0; mt < 2; mt++) {
                    mma16816(s[mt][2 * nt4],     ah[mt], bh4[0], bh4[2]);
                    mma16816(s[mt][2 * nt4 + 1], ah[mt], bh4[1], bh4[3]);
                    mma16816(s[mt][2 * nt4],     ah[mt], bl4[0], bl4[2]);
                    mma16816(s[mt][2 * nt4 + 1], ah[mt], bl4[1], bl4[3]);
                    mma16816(s[mt][2 * nt4],     al[mt], bh4[0], bh4[2]);
                    mma16816(s[mt][2 * nt4 + 1], al[mt], bh4[1], bh4[3]);
                }
            }
        }

        // ---- softmax numerator epilogue ----
#pragma unroll
        for (int mt = 0; mt < 2; mt++) {
#pragma unroll
            for (int nt = 0; nt < 8; nt++) {
                int kcol = wn * 64 + nt * 8 + lc2;
                size_t gk = (size_t)ktbase + kcol;
#pragma unroll
                for (int half = 0; half < 2; half++) {
                    int ql = wm * 32 + mt * 16 + lrq + half * 8;
                    size_t qg = (size_t)qb * 128 + ql;
                    float2 mv = *(const float2*)&mask[((size_t)b * Sq + qg) * Sq + gk];
                    float e0 = __expf(s[mt][nt][half * 2 + 0] * 0.125f + mv.x * (-1e9f));
                    float e1 = __expf(s[mt][nt][half * 2 + 1] * 0.125f + mv.y * (-1e9f));
                    *(float2*)&wout[((size_t)bh * Sq + qg) * Sq + gk] = make_float2(e0, e1);
                    float h0 = bf16hi(e0), h1 = bf16hi(e1);
                    *(uint32_t*)(smb + OEH + (ql * ELD + kcol) * 2) = pack2bf16(e0, e1);
                    *(uint32_t*)(smb + OEL + (ql * ELD + kcol) * 2) = pack2bf16(e0 - h0, e1 - h1);
                    rsum[mt][half] += e0 + e1;
                }
            }
        }
        __syncthreads();

        // ---- AV: accA += E[128q x 128k] * V[128k x 64d] ----
#pragma unroll
        for (int kk8 = 0; kk8 < 8; kk8++) {
            const int kk = kk8 * 16;
            uint32_t eh[2][4], el[2][4];
#pragma unroll
            for (int mt = 0; mt < 2; mt++) {
                uint32_t off = (uint32_t)((wm * 32 + mt * 16 + lrow) * ELD + kk + lcol) * 2;
                ldmat4(eh[mt], sb + OEH + off);
                ldmat4(el[mt], sb + OEL + off);
            }
#pragma unroll
            for (int dt4 = 0; dt4 < 2; dt4++) {
                uint32_t off = (uint32_t)((kk + lrow) * KLD + wn * 32 + dt4 * 16 + lcol) * 2;
                uint32_t vh4[4], vl4[4];
                ldmat4t(vh4, sb + OVH + off);
                ldmat4t(vl4, sb + OVL + off);
#pragma unroll
                for (int mt = 0; mt < 2; mt++) {
                    mma16816(accA[mt][dt4 * 2],     eh[mt], vh4[0], vh4[1]);
                    mma16816(accA[mt][dt4 * 2 + 1], eh[mt], vh4[2], vh4[3]);
                    mma16816(accA[mt][dt4 * 2],     eh[mt], vl4[0], vl4[1]);
                    mma16816(accA[mt][dt4 * 2 + 1], eh[mt], vl4[2], vl4[3]);
                    mma16816(accA[mt][dt4 * 2],     el[mt], vh4[0], vh4[1]);
                    mma16816(accA[mt][dt4 * 2 + 1], el[mt], vh4[2], vh4[3]);
                }
            }
        }
        __syncthreads();
    }

    // ---- rowsum reduction ----
#pragma unroll
    for (int mt = 0; mt < 2; mt++)
#pragma unroll
        for (int half = 0; half < 2; half++) {
            float r = rsum[mt][half];
            r += __shfl_xor_sync(0xFFFFFFFFu, r, 1);
            r += __shfl_xor_sync(0xFFFFFFFFu, r, 2);
            if ((lane & 3) == 0)
                RS[(wm * 32 + mt * 16 + lrq + half * 8) * 2 + wn] = r;
        }
    __syncthreads();
    if (tid < 128) {
        float tot = RS[tid * 2] + RS[tid * 2 + 1];
        g_rowsum[(size_t)bh * Sq + qb * 128 + tid] = tot;
        RS[tid * 2] = 1.0f / tot;
    }
    __syncthreads();

    // ---- store normalized attention output ----
#pragma unroll
    for (int mt = 0; mt < 2; mt++)
#pragma unroll
        for (int dt = 0; dt < 4; dt++) {
            int dcol = wn * 32 + dt * 8 + lc2;
#pragma unroll
            for (int half = 0; half < 2; half++) {
                int ql = wm * 32 + mt * 16 + lrq + half * 8;
                float inv = RS[ql * 2];
                size_t qg = (size_t)qb * 128 + ql;
                float2 o = make_float2(accA[mt][dt][half * 2] * inv,
                                       accA[mt][dt][half * 2 + 1] * inv);
                *(float2*)&g_attn[((size_t)b * Sq + qg) * Dm + h * 64 + dcol] = o;
            }
        }
}

// ---------------------------------------------------------------------------
__global__ __launch_bounds__(128) void norm_kernel(float* __restrict__ w)
{
    int row = blockIdx.x;
    float inv = 1.0f / g_rowsum[row];
    float4* p = (float4*)(w + (size_t)row * Sq);
#pragma unroll
    for (int t = threadIdx.x; t < Sq / 4; t += 128) {
        float4 v = p[t];
        v.x *= inv; v.y *= inv; v.z *= inv; v.w *= inv;
        p[t] = v;
    }
}

// ---------------------------------------------------------------------------
extern "C" void kernel_launch(void* const* d_in, const int* in_sizes, int n_in,
                              void* d_out, int out_size)
{
    const float* q    = (const float*)d_in[0];
    const float* v    = (const float*)d_in[1];
    const float* k    = (const float*)d_in[2];
    const float* mask = (const float*)d_in[3];
    const float* wq_w = (const float*)d_in[4];
    const float* wq_b = (const float*)d_in[5];
    const float* wk_w = (const float*)d_in[6];
    const float* wk_b = (const float*)d_in[7];
    const float* wv_w = (const float*)d_in[8];
    const float* wv_b = (const float*)d_in[9];
    const float* dw   = (const float*)d_in[10];
    const float* db   = (const float*)d_in[11];

    float* out     = (float*)d_out;
    float* weights = out + (size_t)Mrows * Dm;

    __nv_bfloat16 *qhh, *qhl, *khh, *khl, *vhh, *vhl;
    float* attn;
    cudaGetSymbolAddress((void**)&qhh, g_qhh);
    cudaGetSymbolAddress((void**)&qhl, g_qhl);
    cudaGetSymbolAddress((void**)&khh, g_khh);
    cudaGetSymbolAddress((void**)&khl, g_khl);
    cudaGetSymbolAddress((void**)&vhh, g_vhh);
    cudaGetSymbolAddress((void**)&vhl, g_vhl);
    cudaGetSymbolAddress((void**)&attn, g_attn);

    dim3 g(Dm / 128, Mrows / 128);   // (8, 32)

    tc_gemm<<<g, 256>>>(q, wq_w, wq_b, nullptr, qhh, qhl, 1);
    tc_gemm<<<g, 256>>>(k, wk_w, wk_b, nullptr, khh, khl, 1);
    tc_gemm<<<g, 256>>>(v, wv_w, wv_b, nullptr, vhh, vhl, 1);

    cudaFuncSetAttribute(attn_tc, cudaFuncAttributeMaxDynamicSharedMemorySize, ASMEM);
    attn_tc<<<dim3(Sq / 128, BH), 256, ASMEM>>>(mask, weights);

    norm_kernel<<<BH * Sq, 128>>>(weights);

    tc_gemm<<<g, 256>>>(attn, dw, db, out, nullptr, nullptr, 0);
}

// round 9
// speedup vs baseline: 1.5074x; 1.0773x over previous
#include <cuda_runtime.h>
#include <cuda_bf16.h>
#include <math.h>
#include <stdint.h>

// Problem constants
#define Bq 2
#define Sq 2048
#define Dm 1024
#define Hn 16
#define DP 64
#define BH (Bq * Hn)       // 32
#define Mrows (Bq * Sq)    // 4096

// Scratch (device globals: no allocation allowed)
__device__ __nv_bfloat16 g_qhh[BH * Sq * DP];   // [bh][s][d] hi plane
__device__ __nv_bfloat16 g_qhl[BH * Sq * DP];   // lo plane
__device__ __nv_bfloat16 g_khh[BH * Sq * DP];
__device__ __nv_bfloat16 g_khl[BH * Sq * DP];
__device__ __nv_bfloat16 g_vhh[BH * Sq * DP];
__device__ __nv_bfloat16 g_vhl[BH * Sq * DP];
__device__ float g_attn[Mrows * Dm];    // attention output, [b][s][h*64+d]
__device__ float g_rowsum[BH * Sq];     // softmax denominators

__device__ __forceinline__ uint32_t smem_u32(const void* p) {
    uint32_t a;
    asm("{ .reg .u64 t; cvta.to.shared.u64 t, %1; cvt.u32.u64 %0, t; }"
        : "=r"(a) : "l"(p));
    return a;
}
__device__ __forceinline__ void ldmat4(uint32_t* f, uint32_t addr) {
    asm volatile("ldmatrix.sync.aligned.m8n8.x4.shared.b16 {%0,%1,%2,%3}, [%4];"
                 : "=r"(f[0]), "=r"(f[1]), "=r"(f[2]), "=r"(f[3]) : "r"(addr));
}
__device__ __forceinline__ void ldmat4t(uint32_t* f, uint32_t addr) {
    asm volatile("ldmatrix.sync.aligned.m8n8.x4.trans.shared.b16 {%0,%1,%2,%3}, [%4];"
                 : "=r"(f[0]), "=r"(f[1]), "=r"(f[2]), "=r"(f[3]) : "r"(addr));
}
__device__ __forceinline__ void mma16816(float* d, const uint32_t* a,
                                         uint32_t b0, uint32_t b1) {
    asm volatile(
        "mma.sync.aligned.m16n8k16.row.col.f32.bf16.bf16.f32 "
        "{%0,%1,%2,%3}, {%4,%5,%6,%7}, {%8,%9}, {%0,%1,%2,%3};"
        : "+f"(d[0]), "+f"(d[1]), "+f"(d[2]), "+f"(d[3])
        : "r"(a[0]), "r"(a[1]), "r"(a[2]), "r"(a[3]), "r"(b0), "r"(b1));
}
__device__ __forceinline__ uint32_t pack2bf16(float x, float y) {
    __nv_bfloat162 h = __floats2bfloat162_rn(x, y);
    return *(uint32_t*)&h;
}
__device__ __forceinline__ float bf16hi(float x) {
    return __bfloat162float(__float2bfloat16_rn(x));
}
__device__ __forceinline__ void cp16(uint32_t dst, const void* src) {
    asm volatile("cp.async.cg.shared.global [%0], [%1], 16;"
                 :: "r"(dst), "l"(src));
}
#define CP_COMMIT() asm volatile("cp.async.commit_group;" ::: "memory")
#define CP_WAIT0()  asm volatile("cp.async.wait_group 0;" ::: "memory")

// ===========================================================================
// mma.sync bf16-split GEMM: C = A[4096,1024] @ W[1024,1024]^T + bias.
// headSplit=1: write head-split bf16 hi/lo planes (CH/CL); else fp32 C.
// ===========================================================================
#define LDB 40   // bf16 elements per smem row (32 data + 8 pad)

__global__ __launch_bounds__(256, 2) void tc_gemm(
    const float* __restrict__ A, const float* __restrict__ W,
    const float* __restrict__ bias, float* __restrict__ C,
    __nv_bfloat16* __restrict__ CH, __nv_bfloat16* __restrict__ CL,
    int headSplit)
{
    __shared__ __nv_bfloat16 AH[128 * LDB];
    __shared__ __nv_bfloat16 AL[128 * LDB];
    __shared__ __nv_bfloat16 WH[128 * LDB];
    __shared__ __nv_bfloat16 WL[128 * LDB];

    const int tid = threadIdx.x;
    const int wid = tid >> 5, lane = tid & 31;
    const int wm = wid & 3, wn = wid >> 2;
    const int m0 = blockIdx.y * 128, n0 = blockIdx.x * 128;

    const uint32_t sAH = smem_u32(AH), sAL = smem_u32(AL);
    const uint32_t sWH = smem_u32(WH), sWL = smem_u32(WL);

    const int lr = tid >> 1;
    const int lko = (tid & 1) * 16;
    const float* aptr = A + (size_t)(m0 + lr) * Dm + lko;
    const float* wptr = W + (size_t)(n0 + lr) * Dm + lko;
    __nv_bfloat16* pAH = AH + lr * LDB + lko;
    __nv_bfloat16* pAL = AL + lr * LDB + lko;
    __nv_bfloat16* pWH = WH + lr * LDB + lko;
    __nv_bfloat16* pWL = WL + lr * LDB + lko;

    float acc[2][8][4];
#pragma unroll
    for (int i = 0; i < 2; i++)
#pragma unroll
        for (int j = 0; j < 8; j++)
#pragma unroll
            for (int x = 0; x < 4; x++) acc[i][j][x] = 0.0f;

    const int lrow = lane & 15;
    const int lcol = (lane >> 4) << 3;

    for (int t = 0; t < 32; t++) {
        const int kt = t * 32;
        {
            float v[16];
#pragma unroll
            for (int q4 = 0; q4 < 4; q4++)
                *(float4*)&v[q4 * 4] = *(const float4*)&aptr[kt + q4 * 4];
            uint32_t hi[8], lo[8];
#pragma unroll
            for (int e = 0; e < 8; e++) {
                float h0 = bf16hi(v[2 * e]), h1 = bf16hi(v[2 * e + 1]);
                hi[e] = pack2bf16(v[2 * e], v[2 * e + 1]);
                lo[e] = pack2bf16(v[2 * e] - h0, v[2 * e + 1] - h1);
            }
            *(uint4*)pAH = make_uint4(hi[0], hi[1], hi[2], hi[3]);
            *(uint4*)(pAH + 8) = make_uint4(hi[4], hi[5], hi[6], hi[7]);
            *(uint4*)pAL = make_uint4(lo[0], lo[1], lo[2], lo[3]);
            *(uint4*)(pAL + 8) = make_uint4(lo[4], lo[5], lo[6], lo[7]);

#pragma unroll
            for (int q4 = 0; q4 < 4; q4++)
                *(float4*)&v[q4 * 4] = *(const float4*)&wptr[kt + q4 * 4];
#pragma unroll
            for (int e = 0; e < 8; e++) {
                float h0 = bf16hi(v[2 * e]), h1 = bf16hi(v[2 * e + 1]);
                hi[e] = pack2bf16(v[2 * e], v[2 * e + 1]);
                lo[e] = pack2bf16(v[2 * e] - h0, v[2 * e + 1] - h1);
            }
            *(uint4*)pWH = make_uint4(hi[0], hi[1], hi[2], hi[3]);
            *(uint4*)(pWH + 8) = make_uint4(hi[4], hi[5], hi[6], hi[7]);
            *(uint4*)pWL = make_uint4(lo[0], lo[1], lo[2], lo[3]);
            *(uint4*)(pWL + 8) = make_uint4(lo[4], lo[5], lo[6], lo[7]);
        }
        __syncthreads();

#pragma unroll
        for (int kk = 0; kk < 32; kk += 16) {
            uint32_t ah[2][4], al[2][4];
#pragma unroll
            for (int mt = 0; mt < 2; mt++) {
                uint32_t off = (uint32_t)((wm * 32 + mt * 16 + lrow) * LDB + kk + lcol) * 2;
                ldmat4(ah[mt], sAH + off);
                ldmat4(al[mt], sAL + off);
            }
#pragma unroll
            for (int nt4 = 0; nt4 < 4; nt4++) {
                uint32_t off = (uint32_t)((wn * 64 + nt4 * 16 + lrow) * LDB + kk + lcol) * 2;
                uint32_t wh[4], wl[4];
                ldmat4(wh, sWH + off);
                ldmat4(wl, sWL + off);
#pragma unroll
                for (int mt = 0; mt < 2; mt++) {
                    mma16816(acc[mt][2 * nt4],     ah[mt], wh[0], wh[2]);
                    mma16816(acc[mt][2 * nt4 + 1], ah[mt], wh[1], wh[3]);
                    mma16816(acc[mt][2 * nt4],     ah[mt], wl[0], wl[2]);
                    mma16816(acc[mt][2 * nt4 + 1], ah[mt], wl[1], wl[3]);
                    mma16816(acc[mt][2 * nt4],     al[mt], wh[0], wh[2]);
                    mma16816(acc[mt][2 * nt4 + 1], al[mt], wh[1], wh[3]);
                }
            }
        }
        __syncthreads();
    }

    const int lrq = lane >> 2;
    const int lc2 = (lane & 3) * 2;
#pragma unroll
    for (int mt = 0; mt < 2; mt++) {
#pragma unroll
        for (int nt = 0; nt < 8; nt++) {
            int col = n0 + wn * 64 + nt * 8 + lc2;
            float b0 = bias[col], b1 = bias[col + 1];
#pragma unroll
            for (int half = 0; half < 2; half++) {
                int row = m0 + wm * 32 + mt * 16 + lrq + half * 8;
                float ox = acc[mt][nt][half * 2 + 0] + b0;
                float oy = acc[mt][nt][half * 2 + 1] + b1;
                if (!headSplit) {
                    *(float2*)&C[(size_t)row * Dm + col] = make_float2(ox, oy);
                } else {
                    int bb = row >> 11, sI = row & 2047;
                    int h = col >> 6, dd = col & 63;
                    size_t base = ((size_t)(bb * Hn + h) * Sq + sI) * DP + dd;
                    float h0 = bf16hi(ox), h1 = bf16hi(oy);
                    *(uint32_t*)&CH[base] = pack2bf16(ox, oy);
                    *(uint32_t*)&CL[base] = pack2bf16(ox - h0, oy - h1);
                }
            }
        }
    }
}

// ===========================================================================
// Tensor-core fused attention, register-resident E.
// CTA = (bh, 128 q) x 16 k-tiles of 128. Warps: 8m x 1n (16 q-rows each,
// full 128 k-cols) -> QK accumulator fragments ARE the AV A-operand
// fragments (no E smem, 1 sync/tile). K/V double-buffered via cp.async.
// ===========================================================================
#define KLD 72    // bf16 stride for Q/K/V smem rows (64 + 8 pad)
#define OQH 0
#define OQL (128 * KLD * 2)              // 18432
#define OKV0 (2 * 128 * KLD * 2)         // 36864
#define KVBUF (4 * 128 * KLD * 2)        // 73728 (KH,KL,VH,VL)
#define SKH 0
#define SKL (128 * KLD * 2)
#define SVH (2 * 128 * KLD * 2)
#define SVL (3 * 128 * KLD * 2)
#define ORS (OKV0 + 2 * KVBUF)           // 184320
#define ASMEM (ORS + 128 * 4)            // 184832

__global__ __launch_bounds__(256, 1) void attn_tc(
    const float* __restrict__ mask, float* __restrict__ wout)
{
    extern __shared__ char smb[];
    const uint32_t sb = smem_u32(smb);
    float* RS = (float*)(smb + ORS);

    const int tid = threadIdx.x;
    const int wid = tid >> 5, lane = tid & 31;
    const int qb = blockIdx.x;          // 0..15
    const int bh = blockIdx.y;          // 0..31
    const int b = bh >> 4, h = bh & 15;

    const int lrow = lane & 15;
    const int lcol = (lane >> 4) << 3;
    const int lrq = lane >> 2;
    const int lc2 = (lane & 3) * 2;

    const __nv_bfloat16* qHg = g_qhh + ((size_t)bh * Sq + qb * 128) * DP;
    const __nv_bfloat16* qLg = g_qhl + ((size_t)bh * Sq + qb * 128) * DP;
    const __nv_bfloat16* kHg = g_khh + (size_t)bh * Sq * DP;
    const __nv_bfloat16* kLg = g_khl + (size_t)bh * Sq * DP;
    const __nv_bfloat16* vHg = g_vhh + (size_t)bh * Sq * DP;
    const __nv_bfloat16* vLg = g_vhl + (size_t)bh * Sq * DP;

    // loader indices: 4 chunks per thread per array
    const int ldr = tid >> 3;           // row base (tid+i*256)>>3 = ldr + i*32
    const int ldc = (tid & 7) * 8;      // bf16 col

    // ---- prologue: Q + KV tile 0 via cp.async ----
#pragma unroll
    for (int i = 0; i < 4; i++) {
        int r = ldr + i * 32;
        uint32_t so = (uint32_t)(r * KLD + ldc) * 2;
        size_t gi = (size_t)r * DP + ldc;
        cp16(sb + OQH + so, qHg + gi);
        cp16(sb + OQL + so, qLg + gi);
        cp16(sb + OKV0 + SKH + so, kHg + gi);
        cp16(sb + OKV0 + SKL + so, kLg + gi);
        cp16(sb + OKV0 + SVH + so, vHg + gi);
        cp16(sb + OKV0 + SVL + so, vLg + gi);
    }
    CP_COMMIT();

    float accA[8][4];
#pragma unroll
    for (int j = 0; j < 8; j++)
#pragma unroll
        for (int x = 0; x < 4; x++) accA[j][x] = 0.0f;
    float rsum[2] = {0.f, 0.f};

    const int qrow0 = wid * 16;   // this warp's q-row base

    for (int kt = 0; kt < 16; kt++) {
        CP_WAIT0();
        __syncthreads();

        const uint32_t kvo = sb + OKV0 + (kt & 1) * KVBUF;

        // prefetch next tile
        if (kt < 15) {
            const uint32_t nxt = sb + OKV0 + ((kt + 1) & 1) * KVBUF;
            const size_t gbase = (size_t)(kt + 1) * 128 * DP;
#pragma unroll
            for (int i = 0; i < 4; i++) {
                int r = ldr + i * 32;
                uint32_t so = (uint32_t)(r * KLD + ldc) * 2;
                size_t gi = gbase + (size_t)r * DP + ldc;
                cp16(nxt + SKH + so, kHg + gi);
                cp16(nxt + SKL + so, kLg + gi);
                cp16(nxt + SVH + so, vHg + gi);
                cp16(nxt + SVL + so, vLg + gi);
            }
            CP_COMMIT();
        }

        // ---- QK^T: s[16 n8-tiles][4] ----
        float s[16][4];
#pragma unroll
        for (int j = 0; j < 16; j++)
#pragma unroll
            for (int x = 0; x < 4; x++) s[j][x] = 0.0f;

#pragma unroll
        for (int kk = 0; kk < 64; kk += 16) {
            uint32_t ah[4], al[4];
            uint32_t qoff = (uint32_t)((qrow0 + lrow) * KLD + kk + lcol) * 2;
            ldmat4(ah, sb + OQH + qoff);
            ldmat4(al, sb + OQL + qoff);
#pragma unroll
            for (int nt4 = 0; nt4 < 8; nt4++) {
                uint32_t koff = (uint32_t)((nt4 * 16 + lrow) * KLD + kk + lcol) * 2;
                uint32_t bh4[4], bl4[4];
                ldmat4(bh4, kvo + SKH + koff);
                ldmat4(bl4, kvo + SKL + koff);
                mma16816(s[2 * nt4],     ah, bh4[0], bh4[2]);
                mma16816(s[2 * nt4 + 1], ah, bh4[1], bh4[3]);
                mma16816(s[2 * nt4],     ah, bl4[0], bl4[2]);
                mma16816(s[2 * nt4 + 1], ah, bl4[1], bl4[3]);
                mma16816(s[2 * nt4],     al, bh4[0], bh4[2]);
                mma16816(s[2 * nt4 + 1], al, bh4[1], bh4[3]);
            }
        }

        // ---- epilogue: exp/mask -> wout; build AV A-fragments in regs ----
        uint32_t eh[8][4], el[8][4];
        const int ktbase = kt * 128;
#pragma unroll
        for (int j = 0; j < 16; j++) {
#pragma unroll
            for (int half = 0; half < 2; half++) {
                int ql = qrow0 + lrq + half * 8;
                size_t qg = (size_t)qb * 128 + ql;
                size_t gk = (size_t)ktbase + j * 8 + lc2;
                float2 mv = *(const float2*)&mask[((size_t)b * Sq + qg) * Sq + gk];
                float e0 = __expf(s[j][half * 2 + 0] * 0.125f + mv.x * (-1e9f));
                float e1 = __expf(s[j][half * 2 + 1] * 0.125f + mv.y * (-1e9f));
                *(float2*)&wout[((size_t)bh * Sq + qg) * Sq + gk] = make_float2(e0, e1);
                float h0 = bf16hi(e0), h1 = bf16hi(e1);
                eh[j >> 1][(j & 1) * 2 + half] = pack2bf16(e0, e1);
                el[j >> 1][(j & 1) * 2 + half] = pack2bf16(e0 - h0, e1 - h1);
                rsum[half] += e0 + e1;
            }
        }

        // ---- AV: accA[8 d8-tiles][4] += E * V ----
#pragma unroll
        for (int kk8 = 0; kk8 < 8; kk8++) {
#pragma unroll
            for (int dt4 = 0; dt4 < 4; dt4++) {
                uint32_t voff = (uint32_t)((kk8 * 16 + lrow) * KLD + dt4 * 16 + lcol) * 2;
                uint32_t vh4[4], vl4[4];
                ldmat4t(vh4, kvo + SVH + voff);
                ldmat4t(vl4, kvo + SVL + voff);
                mma16816(accA[dt4 * 2],     eh[kk8], vh4[0], vh4[1]);
                mma16816(accA[dt4 * 2 + 1], eh[kk8], vh4[2], vh4[3]);
                mma16816(accA[dt4 * 2],     eh[kk8], vl4[0], vl4[1]);
                mma16816(accA[dt4 * 2 + 1], eh[kk8], vl4[2], vl4[3]);
                mma16816(accA[dt4 * 2],     el[kk8], vh4[0], vh4[1]);
                mma16816(accA[dt4 * 2 + 1], el[kk8], vh4[2], vh4[3]);
            }
        }
    }

    // ---- rowsum reduction (each warp owns rows qrow0..+15) ----
#pragma unroll
    for (int half = 0; half < 2; half++) {
        float r = rsum[half];
        r += __shfl_xor_sync(0xFFFFFFFFu, r, 1);
        r += __shfl_xor_sync(0xFFFFFFFFu, r, 2);
        if ((lane & 3) == 0) RS[qrow0 + lrq + half * 8] = r;
    }
    __syncthreads();
    if (tid < 128) {
        float tot = RS[tid];
        g_rowsum[(size_t)bh * Sq + qb * 128 + tid] = tot;
        RS[tid] = 1.0f / tot;
    }
    __syncthreads();

    // ---- store normalized attention output ----
#pragma unroll
    for (int nt = 0; nt < 8; nt++) {
        int dcol = nt * 8 + lc2;
#pragma unroll
        for (int half = 0; half < 2; half++) {
            int ql = qrow0 + lrq + half * 8;
            float inv = RS[ql];
            size_t qg = (size_t)qb * 128 + ql;
            float2 o = make_float2(accA[nt][half * 2] * inv,
                                   accA[nt][half * 2 + 1] * inv);
            *(float2*)&g_attn[((size_t)b * Sq + qg) * Dm + h * 64 + dcol] = o;
        }
    }
}

// ---------------------------------------------------------------------------
__global__ __launch_bounds__(128) void norm_kernel(float* __restrict__ w)
{
    int row = blockIdx.x;
    float inv = 1.0f / g_rowsum[row];
    float4* p = (float4*)(w + (size_t)row * Sq);
#pragma unroll
    for (int t = threadIdx.x; t < Sq / 4; t += 128) {
        float4 v = p[t];
        v.x *= inv; v.y *= inv; v.z *= inv; v.w *= inv;
        p[t] = v;
    }
}

// ---------------------------------------------------------------------------
extern "C" void kernel_launch(void* const* d_in, const int* in_sizes, int n_in,
                              void* d_out, int out_size)
{
    const float* q    = (const float*)d_in[0];
    const float* v    = (const float*)d_in[1];
    const float* k    = (const float*)d_in[2];
    const float* mask = (const float*)d_in[3];
    const float* wq_w = (const float*)d_in[4];
    const float* wq_b = (const float*)d_in[5];
    const float* wk_w = (const float*)d_in[6];
    const float* wk_b = (const float*)d_in[7];
    const float* wv_w = (const float*)d_in[8];
    const float* wv_b = (const float*)d_in[9];
    const float* dw   = (const float*)d_in[10];
    const float* db   = (const float*)d_in[11];

    float* out     = (float*)d_out;
    float* weights = out + (size_t)Mrows * Dm;

    __nv_bfloat16 *qhh, *qhl, *khh, *khl, *vhh, *vhl;
    float* attn;
    cudaGetSymbolAddress((void**)&qhh, g_qhh);
    cudaGetSymbolAddress((void**)&qhl, g_qhl);
    cudaGetSymbolAddress((void**)&khh, g_khh);
    cudaGetSymbolAddress((void**)&khl, g_khl);
    cudaGetSymbolAddress((void**)&vhh, g_vhh);
    cudaGetSymbolAddress((void**)&vhl, g_vhl);
    cudaGetSymbolAddress((void**)&attn, g_attn);

    dim3 g(Dm / 128, Mrows / 128);   // (8, 32)

    tc_gemm<<<g, 256>>>(q, wq_w, wq_b, nullptr, qhh, qhl, 1);
    tc_gemm<<<g, 256>>>(k, wk_w, wk_b, nullptr, khh, khl, 1);
    tc_gemm<<<g, 256>>>(v, wv_w, wv_b, nullptr, vhh, vhl, 1);

    cudaFuncSetAttribute(attn_tc, cudaFuncAttributeMaxDynamicSharedMemorySize, ASMEM);
    attn_tc<<<dim3(Sq / 128, BH), 256, ASMEM>>>(mask, weights);

    norm_kernel<<<BH * Sq, 128>>>(weights);

    tc_gemm<<<g, 256>>>(attn, dw, db, out, nullptr, nullptr, 0);
}